// round 15
// baseline (speedup 1.0000x reference)
#include <cuda_runtime.h>
#include <cuda_fp16.h>
#include <cstdint>

// ---------------- problem constants ----------------
#define B_SZ   4
#define C_IN   32
#define C_OUT  32
#define HW_DIM 256
#define PLANE  (HW_DIM * HW_DIM)
#define KTAPS  9

// conv tile: 32 cols x 8 rows per block, 256 threads = 8 warps (1 row/warp)
// small tile -> 32 acc regs/thread -> 3 blocks/SM (24 warps)
#define TW 32
#define TH 8
#define IW 34
#define IH 10
#define POS (IH * IW)              // 340
#define NTHREADS 256
#define PBYTES 80                  // 64 data bytes + 16 pad (LDSM conflict-free)

#define SU_BYTES   (POS * PBYTES)          // 27200
#define SWF_OFF    SU_BYTES                // B frags: [chunk18][pair2][lane32] uint4
#define SWF_BYTES  (18 * 2 * 32 * 16)      // 18432
#define SBIAS_OFF  (SWF_OFF + SWF_BYTES)   // 45632
#define SMEM_BYTES (SBIAS_OFF + 128)       // 45760 -> 3 blocks/SM

// pre-scaled fp16 u field, NHWC32, NATURAL k order (k0..k31 consecutive)
__device__ __half g_Uh[(size_t)B_SZ * PLANE * 32];   // 16.8 MB

// ---------------- helpers ----------------
__device__ __forceinline__ unsigned su32(const void* p) {
    return (unsigned)__cvta_generic_to_shared(p);
}
__device__ __forceinline__ void cp16(unsigned d, const void* s, int sz) {
    asm volatile("cp.async.ca.shared.global [%0], [%1], 16, %2;" :: "r"(d), "l"(s), "r"(sz));
}
__device__ __forceinline__ void mma_f16(float* c, unsigned a0, unsigned a1,
                                        unsigned a2, unsigned a3,
                                        unsigned b0, unsigned b1) {
    asm("mma.sync.aligned.m16n8k16.row.col.f32.f16.f16.f32 "
        "{%0,%1,%2,%3},{%4,%5,%6,%7},{%8,%9},{%0,%1,%2,%3};"
        : "+f"(c[0]), "+f"(c[1]), "+f"(c[2]), "+f"(c[3])
        : "r"(a0), "r"(a1), "r"(a2), "r"(a3), "r"(b0), "r"(b1));
}
__device__ __forceinline__ void ldsm_x4(unsigned* a, unsigned addr) {
    asm volatile("ldmatrix.sync.aligned.m8n8.x4.shared.b16 {%0,%1,%2,%3}, [%4];"
        : "=r"(a[0]), "=r"(a[1]), "=r"(a[2]), "=r"(a[3]) : "r"(addr));
}
__device__ __forceinline__ unsigned h2u(__half2 h) { return *(unsigned*)&h; }

// ---------------- kernel 1: log0 scale -> pre-scaled fp16 field ----------------
__global__ void log0_scale_kernel(const float* __restrict__ x) {
    int pid = blockIdx.x * blockDim.x + threadIdx.x;
    int b = pid >> 16, p = pid & (PLANE - 1);
    const float* xb = x + ((size_t)b * C_IN) * PLANE + p;
    float v[C_IN], ss = 0.f;
#pragma unroll
    for (int c = 0; c < C_IN; c++) { v[c] = xb[(size_t)c << 16]; ss += v[c] * v[c]; }
    float n = fmaxf(sqrtf(ss), 1e-7f);
    float S = atanhf(fminf(0.1f * n, 1.0f - 1e-6f)) / (0.1f * n);

    unsigned w[16];
#pragma unroll
    for (int j = 0; j < 16; j++)
        w[j] = h2u(__floats2half2_rn(S * v[2 * j], S * v[2 * j + 1]));
    uint4* go = (uint4*)(g_Uh + ((((size_t)b) << 16) + p) * 32);
#pragma unroll
    for (int j = 0; j < 4; j++)
        go[j] = make_uint4(w[4 * j], w[4 * j + 1], w[4 * j + 2], w[4 * j + 3]);
}

// ---------------- kernel 2: fp16 m16n8k16 conv + bias + relu + exp0 ----------
__global__ __launch_bounds__(NTHREADS, 3)
void pvconv_kernel(const float* __restrict__ Wk,
                   const float* __restrict__ bias,
                   float* __restrict__ out) {
    extern __shared__ char smc[];
    float* sbias = (float*)(smc + SBIAS_OFF);

    const int tid = threadIdx.x, lane = tid & 31, warp = tid >> 5;
    const int b  = blockIdx.z;
    const int r0 = blockIdx.y * TH;
    const int c0 = blockIdx.x * TW;
    const int q = lane >> 2;      // 0..7
    const int t = lane & 3;       // 0..3

    // --- stage B fragments: [chunk18][pair2][lane32] uint4 = 2 n8's (b0,b1) ---
    for (int idx = tid; idx < 18 * 2 * 32; idx += NTHREADS) {
        int chunk = idx >> 6;
        int pair  = (idx >> 5) & 1;
        int l     = idx & 31;
        int lt = l & 3, lq = l >> 2;
        int tap = chunk >> 1, c16 = chunk & 1;
        const float* w0 = Wk + tap * 1024 + ((pair * 2) * 8 + lq) * 32 + c16 * 16;
        const float* w1 = w0 + 8 * 32;
        uint4 f;
        f.x = h2u(__floats2half2_rn(w0[2 * lt],     w0[2 * lt + 1]));
        f.y = h2u(__floats2half2_rn(w0[2 * lt + 8], w0[2 * lt + 9]));
        f.z = h2u(__floats2half2_rn(w1[2 * lt],     w1[2 * lt + 1]));
        f.w = h2u(__floats2half2_rn(w1[2 * lt + 8], w1[2 * lt + 9]));
        ((uint4*)(smc + SWF_OFF))[idx] = f;
    }
    if (tid < 32) sbias[tid] = bias[tid];

    // --- stage whole u tile (all 32 cin) via cp.async, zfill halo ---
    for (int idx = tid; idx < POS * 4; idx += NTHREADS) {
        int pos = idx >> 2, part = idx & 3;
        int irow = pos / IW, icol = pos - irow * IW;
        int grow = r0 - 1 + irow, gcol = c0 - 1 + icol;
        bool ok = ((unsigned)grow < 256u) && ((unsigned)gcol < 256u);
        const char* src = (const char*)g_Uh +
            ((((size_t)b << 16) + ((ok ? grow : 0) << 8) + (ok ? gcol : 0)) * 64) + part * 16;
        cp16(su32(smc) + pos * PBYTES + part * 16, src, ok ? 16 : 0);
    }
    asm volatile("cp.async.commit_group;" ::: "memory");
    asm volatile("cp.async.wait_group 0;" ::: "memory");
    __syncthreads();

    float acc[2][4][4];
#pragma unroll
    for (int g = 0; g < 2; g++)
#pragma unroll
        for (int n = 0; n < 4; n++)
#pragma unroll
            for (int r = 0; r < 4; r++) acc[g][n][r] = 0.f;

    // ldmatrix per-lane base: row = lane&15 (m within m16), kbyte = (lane>>4)*16
    const unsigned abase0 = su32(smc) + (warp * IW + (lane & 15)) * PBYTES
                            + ((lane >> 4) << 4);
    const uint4* swf4 = (const uint4*)(smc + SWF_OFF) + lane;

    // --- mainloop: 18 chunks, a double-buffer + B prefetch ---
    uint4 bf0 = swf4[0];
    uint4 bf1 = swf4[32];
    unsigned a[2][4];
#pragma unroll
    for (int chunk = 0; chunk < 18; chunk++) {
        const int tap = chunk >> 1, c16 = chunk & 1;
        const int ki = tap / 3, kj = tap - ki * 3;
        const unsigned atap = abase0 + (ki * IW + kj) * PBYTES + (c16 << 5);

        ldsm_x4(a[0], atap);                       // g = 0
        uint4 nb0, nb1;
        if (chunk + 1 < 18) {                      // prefetch next chunk's B
            nb0 = swf4[(chunk + 1) * 64];
            nb1 = swf4[(chunk + 1) * 64 + 32];
        }
        ldsm_x4(a[1], atap + 16 * PBYTES);         // g = 1
#pragma unroll
        for (int g = 0; g < 2; g++) {
            const unsigned* ag = a[g];
            mma_f16(acc[g][0], ag[0], ag[1], ag[2], ag[3], bf0.x, bf0.y);
            mma_f16(acc[g][1], ag[0], ag[1], ag[2], ag[3], bf0.z, bf0.w);
            mma_f16(acc[g][2], ag[0], ag[1], ag[2], ag[3], bf1.x, bf1.y);
            mma_f16(acc[g][3], ag[0], ag[1], ag[2], ag[3], bf1.z, bf1.w);
        }
        if (chunk + 1 < 18) { bf0 = nb0; bf1 = nb1; }
    }

    // bias pairs
    float2 bfrag[4];
#pragma unroll
    for (int n8 = 0; n8 < 4; n8++) bfrag[n8] = ((const float2*)sbias)[n8 * 4 + t];

    // --- epilogue: bias + relu + exp0 (4-lane butterfly), DIRECT stores ---
    float* outb = out + (((size_t)b * C_OUT) << 16) + ((r0 + warp) << 8) + c0;
#pragma unroll
    for (int g = 0; g < 2; g++) {
        float s0 = 0.f, s1 = 0.f;
#pragma unroll
        for (int n8 = 0; n8 < 4; n8++) {
            float2 bbv = bfrag[n8];
            float v0 = fmaxf(acc[g][n8][0] + bbv.x, 0.f);
            float v1 = fmaxf(acc[g][n8][1] + bbv.y, 0.f);
            float v2 = fmaxf(acc[g][n8][2] + bbv.x, 0.f);
            float v3 = fmaxf(acc[g][n8][3] + bbv.y, 0.f);
            s0 += v0 * v0 + v1 * v1;
            s1 += v2 * v2 + v3 * v3;
            acc[g][n8][0] = v0; acc[g][n8][1] = v1;
            acc[g][n8][2] = v2; acc[g][n8][3] = v3;
        }
        s0 += __shfl_xor_sync(0xffffffffu, s0, 1);
        s0 += __shfl_xor_sync(0xffffffffu, s0, 2);
        s1 += __shfl_xor_sync(0xffffffffu, s1, 1);
        s1 += __shfl_xor_sync(0xffffffffu, s1, 2);
        float n0 = fmaxf(sqrtf(s0), 1e-7f);
        float n1 = fmaxf(sqrtf(s1), 1e-7f);
        float f0 = tanhf(0.1f * n0) / (0.1f * n0);
        float f1 = tanhf(0.1f * n1) / (0.1f * n1);
        float* pA = outb + g * 16 + q;       // colA
        float* pB = pA + 8;                  // colB
#pragma unroll
        for (int n8 = 0; n8 < 4; n8++) {
            const size_t co0 = (size_t)(n8 * 8 + 2 * t) << 16;
            const size_t co1 = co0 + (1ull << 16);
            pA[co0] = f0 * acc[g][n8][0];
            pA[co1] = f0 * acc[g][n8][1];
            pB[co0] = f1 * acc[g][n8][2];
            pB[co1] = f1 * acc[g][n8][3];
        }
    }
}

// ---------------- launch ----------------
extern "C" void kernel_launch(void* const* d_in, const int* in_sizes, int n_in,
                              void* d_out, int out_size) {
    const float* x    = (const float*)d_in[0];
    const float* Wk   = (const float*)d_in[1];
    const float* bias = (const float*)d_in[2];
    float* out = (float*)d_out;

    cudaFuncSetAttribute(pvconv_kernel,
                         cudaFuncAttributeMaxDynamicSharedMemorySize, SMEM_BYTES);

    // kernel 1: per-pixel log0 scale -> pre-scaled fp16 NHWC32 field
    log0_scale_kernel<<<(B_SZ * PLANE) / 256, 256>>>(x);

    // kernel 2: fp16 tensor-core conv + bias + relu + exp0
    dim3 grid(HW_DIM / TW, HW_DIM / TH, B_SZ);   // (8, 32, 4) = 1024 blocks
    pvconv_kernel<<<grid, NTHREADS, SMEM_BYTES>>>(Wk, bias, out);
}

// round 16
// speedup vs baseline: 1.2523x; 1.2523x over previous
#include <cuda_runtime.h>
#include <cuda_fp16.h>
#include <cstdint>

// ---------------- problem constants ----------------
#define B_SZ   4
#define C_IN   32
#define C_OUT  32
#define HW_DIM 256
#define PLANE  (HW_DIM * HW_DIM)
#define KTAPS  9

// conv tile: 64 cols x 8 rows per block, 256 threads = 8 warps (1 row/warp)
#define TW 64
#define TH 8
#define IW 66
#define IH 10
#define POS (IH * IW)              // 660
#define NTHREADS 256
#define PBYTES 80                  // 64 data bytes + 16 pad (LDSM conflict-free)

#define SU_BYTES   (POS * PBYTES)          // 52800
#define SWF_OFF    SU_BYTES                // B frags: [chunk18][pair2][lane32] uint4
#define SWF_BYTES  (18 * 2 * 32 * 16)      // 18432
#define SBIAS_OFF  (SWF_OFF + SWF_BYTES)   // 71232
#define SMEM_BYTES (SBIAS_OFF + 128)       // 71360 -> 2 blocks/SM

// ---------------- helpers ----------------
__device__ __forceinline__ unsigned su32(const void* p) {
    return (unsigned)__cvta_generic_to_shared(p);
}
__device__ __forceinline__ void mma_f16(float* c, unsigned a0, unsigned a1,
                                        unsigned a2, unsigned a3,
                                        unsigned b0, unsigned b1) {
    asm("mma.sync.aligned.m16n8k16.row.col.f32.f16.f16.f32 "
        "{%0,%1,%2,%3},{%4,%5,%6,%7},{%8,%9},{%0,%1,%2,%3};"
        : "+f"(c[0]), "+f"(c[1]), "+f"(c[2]), "+f"(c[3])
        : "r"(a0), "r"(a1), "r"(a2), "r"(a3), "r"(b0), "r"(b1));
}
__device__ __forceinline__ void ldsm_x4(unsigned* a, unsigned addr) {
    asm volatile("ldmatrix.sync.aligned.m8n8.x4.shared.b16 {%0,%1,%2,%3}, [%4];"
        : "=r"(a[0]), "=r"(a[1]), "=r"(a[2]), "=r"(a[3]) : "r"(addr));
}
__device__ __forceinline__ unsigned h2u(__half2 h) { return *(unsigned*)&h; }

// ---------------- single fused kernel: log0 + conv + bias + relu + exp0 ------
__global__ __launch_bounds__(NTHREADS, 2)
void pvconv_kernel(const float* __restrict__ x,
                   const float* __restrict__ Wk,
                   const float* __restrict__ bias,
                   float* __restrict__ out) {
    extern __shared__ char smc[];
    float* sbias = (float*)(smc + SBIAS_OFF);

    const int tid = threadIdx.x, lane = tid & 31, warp = tid >> 5;
    const int b  = blockIdx.z;
    const int r0 = blockIdx.y * TH;
    const int c0 = blockIdx.x * TW;
    const int q = lane >> 2;      // 0..7
    const int t = lane & 3;       // 0..3

    // --- stage B fragments: [chunk18][pair2][lane32] uint4 = 2 n8's (b0,b1) ---
    for (int idx = tid; idx < 18 * 2 * 32; idx += NTHREADS) {
        int chunk = idx >> 6;
        int pair  = (idx >> 5) & 1;
        int l     = idx & 31;
        int lt = l & 3, lq = l >> 2;
        int tap = chunk >> 1, c16 = chunk & 1;
        const float* w0 = Wk + tap * 1024 + ((pair * 2) * 8 + lq) * 32 + c16 * 16;
        const float* w1 = w0 + 8 * 32;
        uint4 f;
        f.x = h2u(__floats2half2_rn(w0[2 * lt],     w0[2 * lt + 1]));
        f.y = h2u(__floats2half2_rn(w0[2 * lt + 8], w0[2 * lt + 9]));
        f.z = h2u(__floats2half2_rn(w1[2 * lt],     w1[2 * lt + 1]));
        f.w = h2u(__floats2half2_rn(w1[2 * lt + 8], w1[2 * lt + 9]));
        ((uint4*)(smc + SWF_OFF))[idx] = f;
    }
    if (tid < 32) sbias[tid] = bias[tid];

    // --- FUSED staging: load x (fp32, 32 ch), log0 scale, fp16-pack to smem ---
    const float* xb = x + (((size_t)b * C_IN) << 16);
#pragma unroll
    for (int i = 0; i < 3; i++) {
        int p = tid + i * NTHREADS;
        if (p < POS) {
            int irow = p / IW, icol = p - irow * IW;
            int grow = r0 - 1 + irow, gcol = c0 - 1 + icol;
            bool ok = ((unsigned)grow < 256u) && ((unsigned)gcol < 256u);
            uint4 o0 = {0,0,0,0}, o1 = {0,0,0,0}, o2 = {0,0,0,0}, o3 = {0,0,0,0};
            if (ok) {
                const float* xp = xb + (grow << 8) + gcol;
                float v[C_IN], ss = 0.f;
#pragma unroll
                for (int c = 0; c < C_IN; c++) {
                    v[c] = xp[(size_t)c << 16];
                    ss += v[c] * v[c];
                }
                float nn = fmaxf(sqrtf(ss), 1e-7f);
                float S = atanhf(fminf(0.1f * nn, 1.0f - 1e-6f)) / (0.1f * nn);
                unsigned w[16];
#pragma unroll
                for (int j = 0; j < 16; j++)
                    w[j] = h2u(__floats2half2_rn(S * v[2 * j], S * v[2 * j + 1]));
                o0 = make_uint4(w[0],  w[1],  w[2],  w[3]);
                o1 = make_uint4(w[4],  w[5],  w[6],  w[7]);
                o2 = make_uint4(w[8],  w[9],  w[10], w[11]);
                o3 = make_uint4(w[12], w[13], w[14], w[15]);
            }
            uint4* d = (uint4*)(smc + p * PBYTES);
            d[0] = o0; d[1] = o1; d[2] = o2; d[3] = o3;
        }
    }
    __syncthreads();

    float acc[4][4][4];
#pragma unroll
    for (int g = 0; g < 4; g++)
#pragma unroll
        for (int n = 0; n < 4; n++)
#pragma unroll
            for (int r = 0; r < 4; r++) acc[g][n][r] = 0.f;

    // ldmatrix per-lane base: row = lane&15 (m within m16), kbyte = (lane>>4)*16
    const unsigned abase0 = su32(smc) + (warp * IW + (lane & 15)) * PBYTES
                            + ((lane >> 4) << 4);
    const uint4* swf4 = (const uint4*)(smc + SWF_OFF) + lane;

    // --- mainloop: 18 chunks (9 taps x 2 k16), fully unrolled ---
#pragma unroll
    for (int tap = 0; tap < KTAPS; tap++) {
        const int ki = tap / 3, kj = tap - ki * 3;
        const unsigned atap = abase0 + (ki * IW + kj) * PBYTES;
#pragma unroll
        for (int c16 = 0; c16 < 2; c16++) {
            const int chunk = tap * 2 + c16;
            uint4 bf0 = swf4[chunk * 64];        // n8 0,1
            uint4 bf1 = swf4[chunk * 64 + 32];   // n8 2,3

            unsigned a[4][4];
#pragma unroll
            for (int g = 0; g < 4; g++)
                ldsm_x4(a[g], atap + g * 16 * PBYTES + c16 * 32);

#pragma unroll
            for (int g = 0; g < 4; g++) {
                mma_f16(acc[g][0], a[g][0], a[g][1], a[g][2], a[g][3], bf0.x, bf0.y);
                mma_f16(acc[g][1], a[g][0], a[g][1], a[g][2], a[g][3], bf0.z, bf0.w);
                mma_f16(acc[g][2], a[g][0], a[g][1], a[g][2], a[g][3], bf1.x, bf1.y);
                mma_f16(acc[g][3], a[g][0], a[g][1], a[g][2], a[g][3], bf1.z, bf1.w);
            }
        }
    }

    // bias pairs
    float2 bfrag[4];
#pragma unroll
    for (int n8 = 0; n8 < 4; n8++) bfrag[n8] = ((const float2*)sbias)[n8 * 4 + t];

    // --- epilogue: bias + relu + exp0 (4-lane butterfly), DIRECT stores ---
    float* outb = out + (((size_t)b * C_OUT) << 16) + ((r0 + warp) << 8) + c0;
#pragma unroll
    for (int g = 0; g < 4; g++) {
        float s0 = 0.f, s1 = 0.f;
#pragma unroll
        for (int n8 = 0; n8 < 4; n8++) {
            float2 bbv = bfrag[n8];
            float v0 = fmaxf(acc[g][n8][0] + bbv.x, 0.f);
            float v1 = fmaxf(acc[g][n8][1] + bbv.y, 0.f);
            float v2 = fmaxf(acc[g][n8][2] + bbv.x, 0.f);
            float v3 = fmaxf(acc[g][n8][3] + bbv.y, 0.f);
            s0 += v0 * v0 + v1 * v1;
            s1 += v2 * v2 + v3 * v3;
            acc[g][n8][0] = v0; acc[g][n8][1] = v1;
            acc[g][n8][2] = v2; acc[g][n8][3] = v3;
        }
        s0 += __shfl_xor_sync(0xffffffffu, s0, 1);
        s0 += __shfl_xor_sync(0xffffffffu, s0, 2);
        s1 += __shfl_xor_sync(0xffffffffu, s1, 1);
        s1 += __shfl_xor_sync(0xffffffffu, s1, 2);
        float n0 = fmaxf(sqrtf(s0), 1e-7f);
        float n1 = fmaxf(sqrtf(s1), 1e-7f);
        float f0 = tanhf(0.1f * n0) / (0.1f * n0);
        float f1 = tanhf(0.1f * n1) / (0.1f * n1);
        float* pA = outb + g * 16 + q;       // colA
        float* pB = pA + 8;                  // colB
#pragma unroll
        for (int n8 = 0; n8 < 4; n8++) {
            const size_t co0 = (size_t)(n8 * 8 + 2 * t) << 16;
            const size_t co1 = co0 + (1ull << 16);
            pA[co0] = f0 * acc[g][n8][0];
            pA[co1] = f0 * acc[g][n8][1];
            pB[co0] = f1 * acc[g][n8][2];
            pB[co1] = f1 * acc[g][n8][3];
        }
    }
}

// ---------------- launch ----------------
extern "C" void kernel_launch(void* const* d_in, const int* in_sizes, int n_in,
                              void* d_out, int out_size) {
    const float* x    = (const float*)d_in[0];
    const float* Wk   = (const float*)d_in[1];
    const float* bias = (const float*)d_in[2];
    float* out = (float*)d_out;

    cudaFuncSetAttribute(pvconv_kernel,
                         cudaFuncAttributeMaxDynamicSharedMemorySize, SMEM_BYTES);

    // single fused kernel: log0 + fp16 conv + bias + relu + exp0
    dim3 grid(HW_DIM / TW, HW_DIM / TH, B_SZ);   // (4, 32, 4) = 512 blocks
    pvconv_kernel<<<grid, NTHREADS, SMEM_BYTES>>>(x, Wk, bias, out);
}

// round 17
// speedup vs baseline: 1.3483x; 1.0767x over previous
#include <cuda_runtime.h>
#include <cuda_fp16.h>
#include <cstdint>

// ---------------- problem constants ----------------
#define B_SZ   4
#define C_IN   32
#define C_OUT  32
#define HW_DIM 256
#define PLANE  (HW_DIM * HW_DIM)
#define KTAPS  9

// conv tile: 64 cols x 8 rows per block, 256 threads = 8 warps (1 row/warp)
#define TW 64
#define TH 8
#define IW 66
#define IH 10
#define POS (IH * IW)              // 660
#define NTHREADS 256
#define PBYTES 80                  // 64 data bytes + 16 pad (LDSM conflict-free)

#define SU_BYTES   (POS * PBYTES)          // 52800
#define SWF_OFF    SU_BYTES                // B frags: [chunk18][pair2][lane32] uint4
#define SWF_BYTES  (18 * 2 * 32 * 16)      // 18432
#define SBIAS_OFF  (SWF_OFF + SWF_BYTES)   // 71232
#define SMEM_BYTES (SBIAS_OFF + 128)       // 71360 -> 2 blocks/SM

// ---------------- helpers ----------------
__device__ __forceinline__ unsigned su32(const void* p) {
    return (unsigned)__cvta_generic_to_shared(p);
}
__device__ __forceinline__ void mma_f16(float* c, unsigned a0, unsigned a1,
                                        unsigned a2, unsigned a3,
                                        unsigned b0, unsigned b1) {
    asm("mma.sync.aligned.m16n8k16.row.col.f32.f16.f16.f32 "
        "{%0,%1,%2,%3},{%4,%5,%6,%7},{%8,%9},{%0,%1,%2,%3};"
        : "+f"(c[0]), "+f"(c[1]), "+f"(c[2]), "+f"(c[3])
        : "r"(a0), "r"(a1), "r"(a2), "r"(a3), "r"(b0), "r"(b1));
}
__device__ __forceinline__ void ldsm_x4(unsigned* a, unsigned addr) {
    asm volatile("ldmatrix.sync.aligned.m8n8.x4.shared.b16 {%0,%1,%2,%3}, [%4];"
        : "=r"(a[0]), "=r"(a[1]), "=r"(a[2]), "=r"(a[3]) : "r"(addr));
}
__device__ __forceinline__ unsigned h2u(__half2 h) { return *(unsigned*)&h; }

// fast atanh(a)/a for a in (0, 0.6]:  0.5*log((1+a)/(1-a)) / a   (MUFU-based)
__device__ __forceinline__ float atanh_over_a(float a) {
    float r = __logf(__fdividef(1.f + a, 1.f - a));
    return 0.5f * r * __frcp_rn(a);
}
// fast tanh(y)/y for y >= 0 (bounded ~12):  (e^{2y}-1)/((e^{2y}+1)*y)
__device__ __forceinline__ float tanh_over_y(float y) {
    float e = __expf(2.f * y);
    return __fdividef(e - 1.f, (e + 1.f) * y);
}

// ---------------- single fused kernel: log0 + conv + bias + relu + exp0 ------
__global__ __launch_bounds__(NTHREADS, 2)
void pvconv_kernel(const float* __restrict__ x,
                   const float* __restrict__ Wk,
                   const float* __restrict__ bias,
                   float* __restrict__ out) {
    extern __shared__ char smc[];
    float* sbias = (float*)(smc + SBIAS_OFF);

    const int tid = threadIdx.x, lane = tid & 31, warp = tid >> 5;
    const int b  = blockIdx.z;
    const int r0 = blockIdx.y * TH;
    const int c0 = blockIdx.x * TW;
    const int q = lane >> 2;      // 0..7
    const int t = lane & 3;       // 0..3

    // --- stage B fragments: [chunk18][pair2][lane32] uint4 = 2 n8's (b0,b1) ---
    for (int idx = tid; idx < 18 * 2 * 32; idx += NTHREADS) {
        int chunk = idx >> 6;
        int pair  = (idx >> 5) & 1;
        int l     = idx & 31;
        int lt = l & 3, lq = l >> 2;
        int tap = chunk >> 1, c16 = chunk & 1;
        const float* w0 = Wk + tap * 1024 + ((pair * 2) * 8 + lq) * 32 + c16 * 16;
        const float* w1 = w0 + 8 * 32;
        uint4 f;
        f.x = h2u(__floats2half2_rn(w0[2 * lt],     w0[2 * lt + 1]));
        f.y = h2u(__floats2half2_rn(w0[2 * lt + 8], w0[2 * lt + 9]));
        f.z = h2u(__floats2half2_rn(w1[2 * lt],     w1[2 * lt + 1]));
        f.w = h2u(__floats2half2_rn(w1[2 * lt + 8], w1[2 * lt + 9]));
        ((uint4*)(smc + SWF_OFF))[idx] = f;
    }
    if (tid < 32) sbias[tid] = bias[tid];

    // --- FUSED staging: load x (fp32, 32 ch), log0 scale, fp16-pack to smem ---
    const float* xb = x + (((size_t)b * C_IN) << 16);
#pragma unroll
    for (int i = 0; i < 3; i++) {
        int p = tid + i * NTHREADS;
        if (p < POS) {
            int irow = p / IW, icol = p - irow * IW;
            int grow = r0 - 1 + irow, gcol = c0 - 1 + icol;
            bool ok = ((unsigned)grow < 256u) && ((unsigned)gcol < 256u);
            uint4 o0 = {0,0,0,0}, o1 = {0,0,0,0}, o2 = {0,0,0,0}, o3 = {0,0,0,0};
            if (ok) {
                const float* xp = xb + (grow << 8) + gcol;
                float v[C_IN], ss = 0.f;
#pragma unroll
                for (int c = 0; c < C_IN; c++) {
                    v[c] = xp[(size_t)c << 16];
                    ss += v[c] * v[c];
                }
                float nn = fmaxf(__fsqrt_rn(ss), 1e-7f);
                float a = fminf(0.1f * nn, 1.0f - 1e-6f);
                float S = atanh_over_a(a);
                unsigned w[16];
#pragma unroll
                for (int j = 0; j < 16; j++)
                    w[j] = h2u(__floats2half2_rn(S * v[2 * j], S * v[2 * j + 1]));
                o0 = make_uint4(w[0],  w[1],  w[2],  w[3]);
                o1 = make_uint4(w[4],  w[5],  w[6],  w[7]);
                o2 = make_uint4(w[8],  w[9],  w[10], w[11]);
                o3 = make_uint4(w[12], w[13], w[14], w[15]);
            }
            uint4* d = (uint4*)(smc + p * PBYTES);
            d[0] = o0; d[1] = o1; d[2] = o2; d[3] = o3;
        }
    }
    __syncthreads();

    float acc[4][4][4];
#pragma unroll
    for (int g = 0; g < 4; g++)
#pragma unroll
        for (int n = 0; n < 4; n++)
#pragma unroll
            for (int r = 0; r < 4; r++) acc[g][n][r] = 0.f;

    // ldmatrix per-lane base: row = lane&15 (m within m16), kbyte = (lane>>4)*16
    const unsigned abase0 = su32(smc) + (warp * IW + (lane & 15)) * PBYTES
                            + ((lane >> 4) << 4);
    const uint4* swf4 = (const uint4*)(smc + SWF_OFF) + lane;

    // --- mainloop: 18 chunks (9 taps x 2 k16), fully unrolled ---
#pragma unroll
    for (int tap = 0; tap < KTAPS; tap++) {
        const int ki = tap / 3, kj = tap - ki * 3;
        const unsigned atap = abase0 + (ki * IW + kj) * PBYTES;
#pragma unroll
        for (int c16 = 0; c16 < 2; c16++) {
            const int chunk = tap * 2 + c16;
            uint4 bf0 = swf4[chunk * 64];        // n8 0,1
            uint4 bf1 = swf4[chunk * 64 + 32];   // n8 2,3

            unsigned a[4][4];
#pragma unroll
            for (int g = 0; g < 4; g++)
                ldsm_x4(a[g], atap + g * 16 * PBYTES + c16 * 32);

#pragma unroll
            for (int g = 0; g < 4; g++) {
                mma_f16(acc[g][0], a[g][0], a[g][1], a[g][2], a[g][3], bf0.x, bf0.y);
                mma_f16(acc[g][1], a[g][0], a[g][1], a[g][2], a[g][3], bf0.z, bf0.w);
                mma_f16(acc[g][2], a[g][0], a[g][1], a[g][2], a[g][3], bf1.x, bf1.y);
                mma_f16(acc[g][3], a[g][0], a[g][1], a[g][2], a[g][3], bf1.z, bf1.w);
            }
        }
    }

    // bias pairs
    float2 bfrag[4];
#pragma unroll
    for (int n8 = 0; n8 < 4; n8++) bfrag[n8] = ((const float2*)sbias)[n8 * 4 + t];

    // --- epilogue: bias + relu + exp0 (4-lane butterfly), DIRECT stores ---
    float* outb = out + (((size_t)b * C_OUT) << 16) + ((r0 + warp) << 8) + c0;
#pragma unroll
    for (int g = 0; g < 4; g++) {
        float s0 = 0.f, s1 = 0.f;
#pragma unroll
        for (int n8 = 0; n8 < 4; n8++) {
            float2 bbv = bfrag[n8];
            float v0 = fmaxf(acc[g][n8][0] + bbv.x, 0.f);
            float v1 = fmaxf(acc[g][n8][1] + bbv.y, 0.f);
            float v2 = fmaxf(acc[g][n8][2] + bbv.x, 0.f);
            float v3 = fmaxf(acc[g][n8][3] + bbv.y, 0.f);
            s0 += v0 * v0 + v1 * v1;
            s1 += v2 * v2 + v3 * v3;
            acc[g][n8][0] = v0; acc[g][n8][1] = v1;
            acc[g][n8][2] = v2; acc[g][n8][3] = v3;
        }
        s0 += __shfl_xor_sync(0xffffffffu, s0, 1);
        s0 += __shfl_xor_sync(0xffffffffu, s0, 2);
        s1 += __shfl_xor_sync(0xffffffffu, s1, 1);
        s1 += __shfl_xor_sync(0xffffffffu, s1, 2);
        float n0 = fmaxf(__fsqrt_rn(s0), 1e-7f);
        float n1 = fmaxf(__fsqrt_rn(s1), 1e-7f);
        float f0 = tanh_over_y(0.1f * n0);
        float f1 = tanh_over_y(0.1f * n1);
        float* pA = outb + g * 16 + q;       // colA
        float* pB = pA + 8;                  // colB
#pragma unroll
        for (int n8 = 0; n8 < 4; n8++) {
            const size_t co0 = (size_t)(n8 * 8 + 2 * t) << 16;
            const size_t co1 = co0 + (1ull << 16);
            pA[co0] = f0 * acc[g][n8][0];
            pA[co1] = f0 * acc[g][n8][1];
            pB[co0] = f1 * acc[g][n8][2];
            pB[co1] = f1 * acc[g][n8][3];
        }
    }
}

// ---------------- launch ----------------
extern "C" void kernel_launch(void* const* d_in, const int* in_sizes, int n_in,
                              void* d_out, int out_size) {
    const float* x    = (const float*)d_in[0];
    const float* Wk   = (const float*)d_in[1];
    const float* bias = (const float*)d_in[2];
    float* out = (float*)d_out;

    cudaFuncSetAttribute(pvconv_kernel,
                         cudaFuncAttributeMaxDynamicSharedMemorySize, SMEM_BYTES);

    // single fused kernel: log0 + fp16 conv + bias + relu + exp0
    dim3 grid(HW_DIM / TW, HW_DIM / TH, B_SZ);   // (4, 32, 4) = 512 blocks
    pvconv_kernel<<<grid, NTHREADS, SMEM_BYTES>>>(x, Wk, bias, out);
}